// round 5
// baseline (speedup 1.0000x reference)
#include <cuda_runtime.h>
#include <math.h>

// Problem constants
#define KK 4
#define BB 2
#define SS 1024
#define DD 1024
#define NROWS (KK*BB*SS)      // 8192 rows of length D
#define BSROWS (BB*SS)        // 2048
#define BSD (BB*SS*DD)        // 2,097,152
#define NBSD (KK*BSD)         // 8,388,608

#define GRID 740              // 5 blocks/SM x 148 SMs: guaranteed wave-1 resident
#define NT 256

// Scratch (allocation-free: device globals; zero-initialized)
__device__ float g_partial2[GRID * 24];   // per-block partials
__device__ float g_inv[NROWS];            // per-row rsqrt(mean(x^2)+eps)
__device__ float g_maps[24];              // [0..15] res_map[n*4+m], [16..19] pre, [20..23] post
__device__ unsigned int g_cnt  = 0;       // phase-1 arrival counter
__device__ unsigned int g_flag = 0;       // maps-ready flag
__device__ unsigned int g_cnt2 = 0;       // exit counter (resets state)

__global__ __launch_bounds__(NT, 5) void k_fused(
    const float* __restrict__ x,
    const float* __restrict__ w,
    const float* __restrict__ ra,   // res_alpha  [row][D][16]
    const float* __restrict__ pa,   // pre_alpha  [row][D][4]
    const float* __restrict__ qa,   // post_alpha [row][D][4]
    const float* __restrict__ rb,
    const float* __restrict__ pb,
    const float* __restrict__ qb,
    float* __restrict__ out)
{
    __shared__ float xn_sh[DD];
    __shared__ float ssw[8];
    __shared__ float red[8 * 24];
    __shared__ float mp[24];
    __shared__ unsigned int s_last;

    const int t   = threadIdx.x;
    const int wid = t >> 5;
    const int ln  = t & 31;
    const int bid = blockIdx.x;

    const float4* x4 = reinterpret_cast<const float4*>(x);
    const float4  wv = reinterpret_cast<const float4*>(w)[t];

    // ======================= PHASE 1: streaming reductions ==================
    float4 accr = make_float4(0.f, 0.f, 0.f, 0.f);
    float4 accp = make_float4(0.f, 0.f, 0.f, 0.f);
    float4 accq = make_float4(0.f, 0.f, 0.f, 0.f);

    float4 xv = x4[(size_t)bid * (DD / 4) + t];   // prefetch first row

    for (int row = bid; row < NROWS; row += GRID) {
        // ---- RMS norm of current row (xv already loaded) ----
        float ss = xv.x*xv.x + xv.y*xv.y + xv.z*xv.z + xv.w*xv.w;
        #pragma unroll
        for (int o = 16; o; o >>= 1) ss += __shfl_xor_sync(0xffffffffu, ss, o);
        if (ln == 0) ssw[wid] = ss;
        __syncthreads();
        float tot = ssw[0]+ssw[1]+ssw[2]+ssw[3]+ssw[4]+ssw[5]+ssw[6]+ssw[7];
        const float inv = rsqrtf(tot * (1.0f / (float)DD) + 1e-6f);
        if (t == 0) g_inv[row] = inv;

        float4 xnv;
        xnv.x = xv.x * inv * wv.x;
        xnv.y = xv.y * inv * wv.y;
        xnv.z = xv.z * inv * wv.z;
        xnv.w = xv.w * inv * wv.w;
        reinterpret_cast<float4*>(xn_sh)[t] = xnv;
        __syncthreads();

        // ---- prefetch next row's x (overlaps the alpha stream) ----
        const int nrow = row + GRID;
        if (nrow < NROWS) xv = x4[(size_t)nrow * (DD / 4) + t];

        // ---- res_alpha: 4096 float4s/row, fully coalesced ----
        const float4* ra4 = reinterpret_cast<const float4*>(ra) + (size_t)row * (DD * 16 / 4);
        #pragma unroll
        for (int i = 0; i < 16; i++) {
            const int j = i * 256 + t;
            float4 v = __ldcs(&ra4[j]);
            float xs = xn_sh[j >> 2];
            accr.x += xs * v.x; accr.y += xs * v.y; accr.z += xs * v.z; accr.w += xs * v.w;
        }
        // ---- pre/post alpha: 1024 float4s each ----
        const float4* pa4 = reinterpret_cast<const float4*>(pa) + (size_t)row * DD;
        const float4* qa4 = reinterpret_cast<const float4*>(qa) + (size_t)row * DD;
        #pragma unroll
        for (int i = 0; i < 4; i++) {
            const int j = i * 256 + t;
            float xs = xn_sh[j];
            float4 v = __ldcs(&pa4[j]);
            accp.x += xs * v.x; accp.y += xs * v.y; accp.z += xs * v.z; accp.w += xs * v.w;
            float4 u = __ldcs(&qa4[j]);
            accq.x += xs * u.x; accq.y += xs * u.y; accq.z += xs * u.z; accq.w += xs * u.w;
        }
        // NOTE: next iteration's first __syncthreads separates these xn_sh reads
        // from the next xn_sh writes.
    }

    // ---- per-block reduction of the 24 accumulators ----
    #pragma unroll
    for (int o = 16; o >= 4; o >>= 1) {
        accr.x += __shfl_xor_sync(0xffffffffu, accr.x, o);
        accr.y += __shfl_xor_sync(0xffffffffu, accr.y, o);
        accr.z += __shfl_xor_sync(0xffffffffu, accr.z, o);
        accr.w += __shfl_xor_sync(0xffffffffu, accr.w, o);
    }
    #pragma unroll
    for (int o = 16; o; o >>= 1) {
        accp.x += __shfl_xor_sync(0xffffffffu, accp.x, o);
        accp.y += __shfl_xor_sync(0xffffffffu, accp.y, o);
        accp.z += __shfl_xor_sync(0xffffffffu, accp.z, o);
        accp.w += __shfl_xor_sync(0xffffffffu, accp.w, o);
        accq.x += __shfl_xor_sync(0xffffffffu, accq.x, o);
        accq.y += __shfl_xor_sync(0xffffffffu, accq.y, o);
        accq.z += __shfl_xor_sync(0xffffffffu, accq.z, o);
        accq.w += __shfl_xor_sync(0xffffffffu, accq.w, o);
    }
    __syncthreads();   // xn_sh no longer needed; also orders red[] writes below
    if (ln < 4) {
        red[wid * 24 + ln * 4 + 0] = accr.x;
        red[wid * 24 + ln * 4 + 1] = accr.y;
        red[wid * 24 + ln * 4 + 2] = accr.z;
        red[wid * 24 + ln * 4 + 3] = accr.w;
    }
    if (ln == 0) {
        red[wid * 24 + 16] = accp.x; red[wid * 24 + 17] = accp.y;
        red[wid * 24 + 18] = accp.z; red[wid * 24 + 19] = accp.w;
        red[wid * 24 + 20] = accq.x; red[wid * 24 + 21] = accq.y;
        red[wid * 24 + 22] = accq.z; red[wid * 24 + 23] = accq.w;
    }
    __syncthreads();
    if (t < 24) {
        float s = 0.f;
        #pragma unroll
        for (int k = 0; k < 8; k++) s += red[k * 24 + t];
        g_partial2[bid * 24 + t] = s;
    }

    // ======================= device-wide barrier =============================
    __threadfence();                         // publish g_partial2 + g_inv
    __syncthreads();
    if (t == 0) s_last = (atomicAdd(&g_cnt, 1u) == GRID - 1u) ? 1u : 0u;
    __syncthreads();

    if (s_last) {
        // ---- final 24-sum: 8 warps, each sums 93 blocks (740 <= 8*93) ----
        float part = 0.f;
        if (ln < 24) {
            const int b0 = wid * 93;
            const int b1 = (b0 + 93 < GRID) ? b0 + 93 : GRID;
            for (int b = b0; b < b1; b++) part += g_partial2[b * 24 + ln];
        }
        if (ln < 24) red[wid * 24 + ln] = part;
        __syncthreads();

        if (wid == 0) {
            float h = 0.f;
            if (ln < 24) {
                #pragma unroll
                for (int k = 0; k < 8; k++) h += red[k * 24 + ln];
            }
            if (ln >= 16 && ln < 20) g_maps[ln] = 1.f / (1.f + __expf(-(1e-4f * h + pb[ln - 16])));
            if (ln >= 20 && ln < 24) g_maps[ln] = 2.f / (1.f + __expf(-(1e-4f * h + qb[ln - 20])));

            // warp-parallel 4x4 Sinkhorn (lane = a*4+b; xor 1,2 rows; 4,8 cols)
            const int bcol = ln & 3;
            float Z = (ln < 16) ? (1e-4f * h + rb[bcol]) * 20.0f : 0.f;
            float u = 0.f, v = 0.f;
            #pragma unroll 1
            for (int it = 0; it < 20; it++) {
                float tr = Z + v;
                float m = fmaxf(tr, __shfl_xor_sync(0xffffffffu, tr, 1));
                m = fmaxf(m, __shfl_xor_sync(0xffffffffu, m, 2));
                float e = __expf(tr - m);
                float s = e + __shfl_xor_sync(0xffffffffu, e, 1);
                s += __shfl_xor_sync(0xffffffffu, s, 2);
                u = -(m + __logf(s));
                float tc = Z + u;
                float m2 = fmaxf(tc, __shfl_xor_sync(0xffffffffu, tc, 4));
                m2 = fmaxf(m2, __shfl_xor_sync(0xffffffffu, m2, 8));
                float e2 = __expf(tc - m2);
                float s2 = e2 + __shfl_xor_sync(0xffffffffu, e2, 4);
                s2 += __shfl_xor_sync(0xffffffffu, s2, 8);
                v = -(m2 + __logf(s2));
            }
            if (ln < 16) g_maps[ln] = __expf(Z + u + v);
            __threadfence();                          // publish g_maps
            if (ln == 0) atomicExch(&g_flag, 1u);     // release
        }
        __syncthreads();
    } else {
        if (t == 0) {
            while (atomicAdd(&g_flag, 0u) == 0u) __nanosleep(128);
        }
        __syncthreads();
    }

    // ======================= PHASE 2: outputs ================================
    if (t < 24) mp[t] = __ldcg(&g_maps[t]);
    __syncthreads();

    float4* o4 = reinterpret_cast<float4*>(out);
    #pragma unroll 1
    for (int j = bid * NT + t; j < BSD / 4; j += GRID * NT) {
        const int bs = j >> 8;     // single bs per (block, iteration)
        float4 xr[4];
        float  iv[4];
        #pragma unroll
        for (int n = 0; n < 4; n++) {
            xr[n] = x4[(size_t)n * (BSD / 4) + j];
            iv[n] = __ldg(&g_inv[n * BSROWS + bs]);   // uniform across block
        }
        float4 xn[4];
        #pragma unroll
        for (int n = 0; n < 4; n++) {
            xn[n].x = xr[n].x * iv[n] * wv.x;
            xn[n].y = xr[n].y * iv[n] * wv.y;
            xn[n].z = xr[n].z * iv[n] * wv.z;
            xn[n].w = xr[n].w * iv[n] * wv.w;
        }
        float4 L = make_float4(0.f, 0.f, 0.f, 0.f);
        #pragma unroll
        for (int n = 0; n < 4; n++) {
            float pc = mp[16 + n];
            L.x += xn[n].x * pc; L.y += xn[n].y * pc; L.z += xn[n].z * pc; L.w += xn[n].w * pc;
        }
        #pragma unroll
        for (int m = 0; m < 4; m++) {
            float4 r = make_float4(0.f, 0.f, 0.f, 0.f);
            #pragma unroll
            for (int n = 0; n < 4; n++) {
                float c = mp[n * 4 + m];
                r.x += xn[n].x * c; r.y += xn[n].y * c; r.z += xn[n].z * c; r.w += xn[n].w * c;
            }
            __stcs(&o4[(size_t)m * (BSD / 4) + j], r);
        }
        #pragma unroll
        for (int n = 0; n < 4; n++) {
            float c = mp[20 + n];
            float4 pv = make_float4(L.x * c, L.y * c, L.z * c, L.w * c);
            __stcs(&o4[(size_t)(NBSD / 4) + (size_t)n * (BSD / 4) + j], pv);
        }
    }

    // ======================= exit: reset barrier state =======================
    __syncthreads();
    if (t == 0) {
        if (atomicAdd(&g_cnt2, 1u) == GRID - 1u) {
            g_cnt = 0; g_flag = 0; g_cnt2 = 0;   // clean slate for next replay
        }
    }
}

// ---------------------------------------------------------------------------
extern "C" void kernel_launch(void* const* d_in, const int* in_sizes, int n_in,
                              void* d_out, int out_size)
{
    const float* x  = (const float*)d_in[0];
    const float* w  = (const float*)d_in[1];
    const float* ra = (const float*)d_in[2];
    const float* pa = (const float*)d_in[3];
    const float* qa = (const float*)d_in[4];
    const float* rb = (const float*)d_in[5];
    const float* pb = (const float*)d_in[6];
    const float* qb = (const float*)d_in[7];
    float* out = (float*)d_out;

    k_fused<<<GRID, NT>>>(x, w, ra, pa, qa, rb, pb, qb, out);
}